// round 2
// baseline (speedup 1.0000x reference)
#include <cuda_runtime.h>

#define NN 50000
#define NE 1600000
#define NG 512
#define DH 128
#define DOUT 64

// ---------------- scratch (static __device__ — no allocations) ----------------
__device__ int                        g_deg[NN];
__device__ float                      g_dinv[NN];
__device__ int                        g_off[NN + 1];
__device__ int                        g_cur[NN];
__device__ int                        g_csr[NE];
__device__ __align__(16) float        g_h[NN * DH];   // h' = dinv * (X @ W)
__device__ __align__(16) float        g_a[NN * DH];   // aggregated / next-layer input
__device__ int                        g_gcnt[NG];
__device__ int                        g_goff[NG + 1];
__device__ float                      g_emb[2][NG * DOUT];

// ---------------- packed fp32x2 helpers (Blackwell FFMA2) ----------------
__device__ __forceinline__ unsigned long long pack_dup(float w) {
    unsigned long long r;
    asm("mov.b64 %0, {%1, %1};" : "=l"(r) : "f"(w));
    return r;
}
__device__ __forceinline__ void ffma2(unsigned long long& d,
                                      unsigned long long a,
                                      unsigned long long b) {
    asm("fma.rn.f32x2 %0, %1, %2, %0;" : "+l"(d) : "l"(a), "l"(b));
}

// ---------------- graph prep ----------------
__global__ void zero_k() {
    int i = blockIdx.x * blockDim.x + threadIdx.x;
    if (i < NN) g_deg[i] = 0;
    if (i < NG) g_gcnt[i] = 0;
}

__global__ void count_k(const int* __restrict__ dst) {
    int e = blockIdx.x * blockDim.x + threadIdx.x;
    if (e < NE) atomicAdd(&g_deg[dst[e]], 1);
}

__global__ void dinv_k() {
    int i = blockIdx.x * blockDim.x + threadIdx.x;
    if (i < NN) g_dinv[i] = rsqrtf((float)(g_deg[i] + 1));  // +1 self-loop
}

// single-block exclusive scan. which=0: deg->off(+cur), which=1: gcnt->goff
__global__ void scan_k(int which) {
    const int* in = which ? g_gcnt : g_deg;
    int* out = which ? g_goff : g_off;
    int* cur = which ? (int*)0 : g_cur;
    int n = which ? NG : NN;

    __shared__ int wsum[32];
    __shared__ int wbase[32];
    __shared__ int carry_s, total_s;
    int t = threadIdx.x;           // 1024 threads
    int lane = t & 31, wid = t >> 5;
    if (t == 0) carry_s = 0;
    __syncthreads();

    for (int base = 0; base < n; base += 1024) {
        int i = base + t;
        int v = (i < n) ? in[i] : 0;
        int incl = v;
#pragma unroll
        for (int o = 1; o < 32; o <<= 1) {
            int x = __shfl_up_sync(0xffffffffu, incl, o);
            if (lane >= o) incl += x;
        }
        if (lane == 31) wsum[wid] = incl;
        __syncthreads();
        if (wid == 0) {
            int wv = wsum[lane];
            int wi = wv;
#pragma unroll
            for (int o = 1; o < 32; o <<= 1) {
                int x = __shfl_up_sync(0xffffffffu, wi, o);
                if (lane >= o) wi += x;
            }
            wbase[lane] = wi - wv;
            if (lane == 31) total_s = wi;
        }
        __syncthreads();
        int excl = carry_s + wbase[wid] + incl - v;
        if (i < n) {
            out[i] = excl;
            if (cur) cur[i] = excl;
        }
        __syncthreads();
        if (t == 0) carry_s += total_s;
        __syncthreads();
    }
    if (t == 0) out[n] = carry_s;
}

__global__ void fill_k(const int* __restrict__ src, const int* __restrict__ dst) {
    int e = blockIdx.x * blockDim.x + threadIdx.x;
    if (e < NE) {
        int p = atomicAdd(&g_cur[dst[e]], 1);
        g_csr[p] = src[e];
    }
}

__global__ void gcount_k(const int* __restrict__ batch) {
    int i = blockIdx.x * blockDim.x + threadIdx.x;
    if (i < NN) atomicAdd(&g_gcnt[batch[i]], 1);
}

// ---------------- GEMM: g_h[i] = dinv[i] * (X[i] @ W)  (50000x128 @ 128x128) ----
// 256 thr, tile 128x128, BK=16. Per-thread 8 rows x 8 cols, row pairs packed for
// fma.rn.f32x2 (32 packed accumulators).
__global__ __launch_bounds__(256) void gemm_k(const float* __restrict__ Xin,
                                              const float* __restrict__ W,
                                              int from_a) {
    const float* __restrict__ X = from_a ? g_a : Xin;
    __shared__ __align__(16) float xs[16][132];  // xs[k][row]
    __shared__ __align__(16) float ws[16][128];  // ws[k][col]

    int row0 = blockIdx.x * 128;
    int t = threadIdx.x;
    int tx = t & 15;   // cols tx*8 .. tx*8+7
    int ty = t >> 4;   // rows ty*8 .. ty*8+7

    unsigned long long acc[4][8];
#pragma unroll
    for (int p = 0; p < 4; p++)
#pragma unroll
        for (int j = 0; j < 8; j++) acc[p][j] = 0ull;

    for (int kk = 0; kk < 8; kk++) {
        __syncthreads();
#pragma unroll
        for (int s = 0; s < 2; s++) {
            int fi = t * 2 + s;  // [0,512)
            int xr = fi >> 2, xq = fi & 3;
            float4 xv = make_float4(0.f, 0.f, 0.f, 0.f);
            int gr = row0 + xr;
            if (gr < NN) xv = *(const float4*)(X + (size_t)gr * DH + kk * 16 + xq * 4);
            xs[xq * 4 + 0][xr] = xv.x;
            xs[xq * 4 + 1][xr] = xv.y;
            xs[xq * 4 + 2][xr] = xv.z;
            xs[xq * 4 + 3][xr] = xv.w;
            int wk = fi >> 5, wq = fi & 31;
            float4 wv = *(const float4*)(W + (size_t)(kk * 16 + wk) * DH + wq * 4);
            *(float4*)&ws[wk][wq * 4] = wv;
        }
        __syncthreads();
#pragma unroll
        for (int k = 0; k < 16; k++) {
            const unsigned long long* xp = (const unsigned long long*)&xs[k][ty * 8];
            unsigned long long x0 = xp[0], x1 = xp[1], x2 = xp[2], x3 = xp[3];
            float4 wa = *(const float4*)&ws[k][tx * 8];
            float4 wb = *(const float4*)&ws[k][tx * 8 + 4];
            unsigned long long wp[8];
            wp[0] = pack_dup(wa.x); wp[1] = pack_dup(wa.y);
            wp[2] = pack_dup(wa.z); wp[3] = pack_dup(wa.w);
            wp[4] = pack_dup(wb.x); wp[5] = pack_dup(wb.y);
            wp[6] = pack_dup(wb.z); wp[7] = pack_dup(wb.w);
#pragma unroll
            for (int j = 0; j < 8; j++) {
                ffma2(acc[0][j], x0, wp[j]);
                ffma2(acc[1][j], x1, wp[j]);
                ffma2(acc[2][j], x2, wp[j]);
                ffma2(acc[3][j], x3, wp[j]);
            }
        }
    }
#pragma unroll
    for (int p = 0; p < 4; p++) {
        float lo[8], hi[8];
#pragma unroll
        for (int j = 0; j < 8; j++) {
            union { unsigned long long u; float2 f; } cv;
            cv.u = acc[p][j];
            lo[j] = cv.f.x;
            hi[j] = cv.f.y;
        }
        int r0 = row0 + ty * 8 + 2 * p;
        if (r0 < NN) {
            float s = g_dinv[r0];
            float4 v0 = make_float4(s * lo[0], s * lo[1], s * lo[2], s * lo[3]);
            float4 v1 = make_float4(s * lo[4], s * lo[5], s * lo[6], s * lo[7]);
            *(float4*)(g_h + (size_t)r0 * DH + tx * 8) = v0;
            *(float4*)(g_h + (size_t)r0 * DH + tx * 8 + 4) = v1;
        }
        int r1 = r0 + 1;
        if (r1 < NN) {
            float s = g_dinv[r1];
            float4 v0 = make_float4(s * hi[0], s * hi[1], s * hi[2], s * hi[3]);
            float4 v1 = make_float4(s * hi[4], s * hi[5], s * hi[6], s * hi[7]);
            *(float4*)(g_h + (size_t)r1 * DH + tx * 8) = v0;
            *(float4*)(g_h + (size_t)r1 * DH + tx * 8 + 4) = v1;
        }
    }
}

// ---------------- aggregation: warp-per-node CSR gather-reduce ----------------
// g_a[i] = act( dinv[i] * (sum_{src in N(i)} g_h[src] + g_h[i]) + b )
__global__ __launch_bounds__(256, 8) void agg_k(const float* __restrict__ bias,
                                                int do_relu) {
    int w = blockIdx.x * 8 + (threadIdx.x >> 5);
    if (w >= NN) return;
    int lane = threadIdx.x & 31;
    const float4* __restrict__ Hv = (const float4*)g_h;

    float4 acc = __ldg(&Hv[(size_t)w * 32 + lane]);  // self-loop term
    int s0 = g_off[w], s1 = g_off[w + 1];
    for (int base = s0; base < s1; base += 32) {
        int e = base + lane;
        int idx = (e < s1) ? __ldg(&g_csr[e]) : 0;
        int m = min(32, s1 - base);
        int j = 0;
        for (; j + 4 <= m; j += 4) {
            int a0 = __shfl_sync(0xffffffffu, idx, j);
            int a1 = __shfl_sync(0xffffffffu, idx, j + 1);
            int a2 = __shfl_sync(0xffffffffu, idx, j + 2);
            int a3 = __shfl_sync(0xffffffffu, idx, j + 3);
            float4 h0 = __ldg(&Hv[(size_t)a0 * 32 + lane]);
            float4 h1 = __ldg(&Hv[(size_t)a1 * 32 + lane]);
            float4 h2 = __ldg(&Hv[(size_t)a2 * 32 + lane]);
            float4 h3 = __ldg(&Hv[(size_t)a3 * 32 + lane]);
            acc.x += (h0.x + h1.x) + (h2.x + h3.x);
            acc.y += (h0.y + h1.y) + (h2.y + h3.y);
            acc.z += (h0.z + h1.z) + (h2.z + h3.z);
            acc.w += (h0.w + h1.w) + (h2.w + h3.w);
        }
        for (; j < m; j++) {
            int a0 = __shfl_sync(0xffffffffu, idx, j);
            float4 h0 = __ldg(&Hv[(size_t)a0 * 32 + lane]);
            acc.x += h0.x; acc.y += h0.y; acc.z += h0.z; acc.w += h0.w;
        }
    }
    float di = g_dinv[w];
    float4 bb = __ldg(&((const float4*)bias)[lane]);
    float4 o;
    o.x = fmaf(di, acc.x, bb.x);
    o.y = fmaf(di, acc.y, bb.y);
    o.z = fmaf(di, acc.z, bb.z);
    o.w = fmaf(di, acc.w, bb.w);
    if (do_relu) {
        o.x = fmaxf(o.x, 0.f); o.y = fmaxf(o.y, 0.f);
        o.z = fmaxf(o.z, 0.f); o.w = fmaxf(o.w, 0.f);
    }
    ((float4*)g_a)[(size_t)w * 32 + lane] = o;
}

// ---------------- fused mean-pool + linear ----------------
__global__ __launch_bounds__(128) void pool_lin_k(const float* __restrict__ Wlin,
                                                  const float* __restrict__ blin,
                                                  int br) {
    int g = blockIdx.x;
    int t = threadIdx.x;  // 128
    int s = g_goff[g], c = g_gcnt[g];
    float sum = 0.f;
    for (int r = s; r < s + c; r++) sum += g_a[(size_t)r * DH + t];
    __shared__ float m[DH];
    m[t] = sum * (1.f / fmaxf((float)c, 1.f));
    __syncthreads();
    if (t < DOUT) {
        float o = blin[t];
#pragma unroll
        for (int f = 0; f < DH; f++) o = fmaf(m[f], Wlin[f * DOUT + t], o);
        g_emb[br][g * DOUT + t] = o;
    }
}

// ---------------- pairwise distance ----------------
__global__ void final_k(float* __restrict__ out) {
    int g = blockIdx.x, lane = threadIdx.x;  // 32 threads
    float d0 = g_emb[0][g * DOUT + lane]      - g_emb[1][g * DOUT + lane]      + 1e-6f;
    float d1 = g_emb[0][g * DOUT + lane + 32] - g_emb[1][g * DOUT + lane + 32] + 1e-6f;
    float s = d0 * d0 + d1 * d1;
#pragma unroll
    for (int o = 16; o; o >>= 1) s += __shfl_xor_sync(0xffffffffu, s, o);
    if (lane == 0) out[g] = sqrtf(s);
}

// ---------------- host driver ----------------
static void run_branch(const float* x, const int* ei, const int* batch,
                       const float* W1, const float* b1,
                       const float* W2, const float* b2,
                       const float* W3, const float* b3,
                       const float* Wl, const float* bl, int br) {
    const int* src = ei;
    const int* dst = ei + NE;

    zero_k<<<(NN + 1023) / 1024, 1024>>>();
    count_k<<<(NE + 511) / 512, 512>>>(dst);
    dinv_k<<<(NN + 255) / 256, 256>>>();
    scan_k<<<1, 1024>>>(0);
    fill_k<<<(NE + 511) / 512, 512>>>(src, dst);

    gemm_k<<<(NN + 127) / 128, 256>>>(x, W1, 0);
    agg_k<<<(NN + 7) / 8, 256>>>(b1, 1);
    gemm_k<<<(NN + 127) / 128, 256>>>(nullptr, W2, 1);
    agg_k<<<(NN + 7) / 8, 256>>>(b2, 1);
    gemm_k<<<(NN + 127) / 128, 256>>>(nullptr, W3, 1);
    agg_k<<<(NN + 7) / 8, 256>>>(b3, 0);

    gcount_k<<<(NN + 255) / 256, 256>>>(batch);
    scan_k<<<1, 1024>>>(1);
    pool_lin_k<<<NG, 128>>>(Wl, bl, br);
}

extern "C" void kernel_launch(void* const* d_in, const int* in_sizes, int n_in,
                              void* d_out, int out_size) {
    const float* x1 = (const float*)d_in[0];
    const int*   e1 = (const int*)d_in[1];
    const int*   t1 = (const int*)d_in[2];
    const float* x2 = (const float*)d_in[3];
    const int*   e2 = (const int*)d_in[4];
    const int*   t2 = (const int*)d_in[5];
    const float* W1 = (const float*)d_in[6];
    const float* b1 = (const float*)d_in[7];
    const float* W2 = (const float*)d_in[8];
    const float* b2 = (const float*)d_in[9];
    const float* W3 = (const float*)d_in[10];
    const float* b3 = (const float*)d_in[11];
    const float* Wl = (const float*)d_in[12];
    const float* bl = (const float*)d_in[13];

    run_branch(x1, e1, t1, W1, b1, W2, b2, W3, b3, Wl, bl, 0);
    run_branch(x2, e2, t2, W1, b1, W2, b2, W3, b3, Wl, bl, 1);
    final_k<<<NG, 32>>>((float*)d_out);
}

// round 4
// speedup vs baseline: 1.2808x; 1.2808x over previous
#include <cuda_runtime.h>
#include <cuda_fp16.h>

#define NN 50000
#define NE 1600000
#define NG 512
#define DH 128
#define DOUT 64

// ---------------- scratch (static __device__ — no allocations) ----------------
__device__ int                        g_deg[NN];
__device__ float                      g_dinv[NN];
__device__ int                        g_off[NN];
__device__ int                        g_cur[NN];
__device__ int                        g_total;
__device__ int                        g_csr[NE];
__device__ __align__(16) __half       g_h[NN * DH];   // h' = dinv * (X @ W), fp16
__device__ __align__(16) float        g_a[NN * DH];   // aggregated / next-layer input
__device__ int                        g_goff[NG + 1];
__device__ float                      g_emb[2][NG * DOUT];

// ---------------- packed fp32x2 helpers (Blackwell FFMA2) ----------------
__device__ __forceinline__ unsigned long long pack_dup(float w) {
    unsigned long long r;
    asm("mov.b64 %0, {%1, %1};" : "=l"(r) : "f"(w));
    return r;
}
__device__ __forceinline__ void ffma2(unsigned long long& d,
                                      unsigned long long a,
                                      unsigned long long b) {
    asm("fma.rn.f32x2 %0, %1, %2, %0;" : "+l"(d) : "l"(a), "l"(b));
}

// ---------------- graph prep ----------------
__global__ void zero_k() {
    int i = blockIdx.x * blockDim.x + threadIdx.x;
    if (i < NN) g_deg[i] = 0;
    if (i == 0) g_total = 0;
}

__global__ void count_k(const int* __restrict__ dst) {
    int e = blockIdx.x * blockDim.x + threadIdx.x;
    if (e < NE) atomicAdd(&g_deg[dst[e]], 1);
}

// scan-free CSR offsets: warp-aggregated atomic chunk assignment + dinv
__global__ void offs_k() {
    int i = blockIdx.x * blockDim.x + threadIdx.x;
    int lane = threadIdx.x & 31;
    int d = (i < NN) ? g_deg[i] : 0;
    int incl = d;
#pragma unroll
    for (int o = 1; o < 32; o <<= 1) {
        int x = __shfl_up_sync(0xffffffffu, incl, o);
        if (lane >= o) incl += x;
    }
    int wsum = __shfl_sync(0xffffffffu, incl, 31);
    int base = 0;
    if (lane == 31) base = atomicAdd(&g_total, wsum);
    base = __shfl_sync(0xffffffffu, base, 31);
    if (i < NN) {
        int p = base + incl - d;
        g_off[i] = p;
        g_cur[i] = p;
        g_dinv[i] = rsqrtf((float)(d + 1));  // +1 self-loop
    }
}

__global__ void fill_k(const int* __restrict__ src, const int* __restrict__ dst) {
    int e = blockIdx.x * blockDim.x + threadIdx.x;
    if (e < NE) {
        int p = atomicAdd(&g_cur[dst[e]], 1);
        g_csr[p] = src[e];
    }
}

// graph segment boundaries from the sorted batch array (no count+scan needed)
__global__ void gbound_k(const int* __restrict__ batch) {
    int i = blockIdx.x * blockDim.x + threadIdx.x;
    if (i >= NN) return;
    int bc = batch[i];
    if (i == 0) {
        for (int g = 0; g <= bc; g++) g_goff[g] = 0;
    } else {
        int bp = batch[i - 1];
        for (int g = bp + 1; g <= bc; g++) g_goff[g] = i;
    }
    if (i == NN - 1) {
        for (int g = bc + 1; g <= NG; g++) g_goff[g] = NN;
    }
}

// ---------------- GEMM: g_h[i] = fp16( dinv[i] * (X[i] @ W) ) ----------------
// 256 thr, tile 128x128, BK=16. Per-thread 8 rows x 8 cols, row pairs packed for
// fma.rn.f32x2 (32 packed accumulators). fp16 epilogue.
__global__ __launch_bounds__(256) void gemm_k(const float* __restrict__ Xin,
                                              const float* __restrict__ W,
                                              int from_a) {
    const float* __restrict__ X = from_a ? g_a : Xin;
    __shared__ __align__(16) float xs[16][132];  // xs[k][row]
    __shared__ __align__(16) float ws[16][128];  // ws[k][col]

    int row0 = blockIdx.x * 128;
    int t = threadIdx.x;
    int tx = t & 15;   // cols tx*8 .. tx*8+7
    int ty = t >> 4;   // rows ty*8 .. ty*8+7

    unsigned long long acc[4][8];
#pragma unroll
    for (int p = 0; p < 4; p++)
#pragma unroll
        for (int j = 0; j < 8; j++) acc[p][j] = 0ull;

    for (int kk = 0; kk < 8; kk++) {
        __syncthreads();
#pragma unroll
        for (int s = 0; s < 2; s++) {
            int fi = t * 2 + s;  // [0,512)
            int xr = fi >> 2, xq = fi & 3;
            float4 xv = make_float4(0.f, 0.f, 0.f, 0.f);
            int gr = row0 + xr;
            if (gr < NN) xv = *(const float4*)(X + (size_t)gr * DH + kk * 16 + xq * 4);
            xs[xq * 4 + 0][xr] = xv.x;
            xs[xq * 4 + 1][xr] = xv.y;
            xs[xq * 4 + 2][xr] = xv.z;
            xs[xq * 4 + 3][xr] = xv.w;
            int wk = fi >> 5, wq = fi & 31;
            float4 wv = *(const float4*)(W + (size_t)(kk * 16 + wk) * DH + wq * 4);
            *(float4*)&ws[wk][wq * 4] = wv;
        }
        __syncthreads();
#pragma unroll
        for (int k = 0; k < 16; k++) {
            const unsigned long long* xp = (const unsigned long long*)&xs[k][ty * 8];
            unsigned long long x0 = xp[0], x1 = xp[1], x2 = xp[2], x3 = xp[3];
            float4 wa = *(const float4*)&ws[k][tx * 8];
            float4 wb = *(const float4*)&ws[k][tx * 8 + 4];
            unsigned long long wp[8];
            wp[0] = pack_dup(wa.x); wp[1] = pack_dup(wa.y);
            wp[2] = pack_dup(wa.z); wp[3] = pack_dup(wa.w);
            wp[4] = pack_dup(wb.x); wp[5] = pack_dup(wb.y);
            wp[6] = pack_dup(wb.z); wp[7] = pack_dup(wb.w);
#pragma unroll
            for (int j = 0; j < 8; j++) {
                ffma2(acc[0][j], x0, wp[j]);
                ffma2(acc[1][j], x1, wp[j]);
                ffma2(acc[2][j], x2, wp[j]);
                ffma2(acc[3][j], x3, wp[j]);
            }
        }
    }
    // epilogue: scale by dinv[row], convert to fp16, one 16B store per row
#pragma unroll
    for (int p = 0; p < 4; p++) {
        float lo[8], hi[8];
#pragma unroll
        for (int j = 0; j < 8; j++) {
            union { unsigned long long u; float2 f; } cv;
            cv.u = acc[p][j];
            lo[j] = cv.f.x;
            hi[j] = cv.f.y;
        }
        int r0 = row0 + ty * 8 + 2 * p;
        if (r0 < NN) {
            float s = g_dinv[r0];
            union { uint4 u; __half2 h[4]; } pk;
            pk.h[0] = __floats2half2_rn(s * lo[0], s * lo[1]);
            pk.h[1] = __floats2half2_rn(s * lo[2], s * lo[3]);
            pk.h[2] = __floats2half2_rn(s * lo[4], s * lo[5]);
            pk.h[3] = __floats2half2_rn(s * lo[6], s * lo[7]);
            ((uint4*)(g_h + (size_t)r0 * DH))[tx] = pk.u;
        }
        int r1 = r0 + 1;
        if (r1 < NN) {
            float s = g_dinv[r1];
            union { uint4 u; __half2 h[4]; } pk;
            pk.h[0] = __floats2half2_rn(s * hi[0], s * hi[1]);
            pk.h[1] = __floats2half2_rn(s * hi[2], s * hi[3]);
            pk.h[2] = __floats2half2_rn(s * hi[4], s * hi[5]);
            pk.h[3] = __floats2half2_rn(s * hi[6], s * hi[7]);
            ((uint4*)(g_h + (size_t)r1 * DH))[tx] = pk.u;
        }
    }
}

// ---------------- aggregation: warp-per-node CSR gather-reduce (fp16 rows) -----
// g_a[i] = act( dinv[i] * (sum_{src in N(i)} h'[src] + h'[i]) + b )
__global__ __launch_bounds__(256, 8) void agg_k(const float* __restrict__ bias,
                                                int do_relu) {
    int w = blockIdx.x * 8 + (threadIdx.x >> 5);
    if (w >= NN) return;
    int lane = threadIdx.x & 31;
    const uint2* __restrict__ Hv = (const uint2*)g_h;  // 4 halves per lane

    union { uint2 u; __half2 h[2]; } v;
    v.u = __ldg(&Hv[(size_t)w * 32 + lane]);  // self-loop term
    float2 f0 = __half22float2(v.h[0]);
    float2 f1 = __half22float2(v.h[1]);
    float4 acc = make_float4(f0.x, f0.y, f1.x, f1.y);

    int s0 = g_off[w];
    int s1 = s0 + g_deg[w];
    for (int base = s0; base < s1; base += 32) {
        int e = base + lane;
        int idx = (e < s1) ? __ldg(&g_csr[e]) : 0;
        int m = min(32, s1 - base);
        int j = 0;
        for (; j + 4 <= m; j += 4) {
            int a0 = __shfl_sync(0xffffffffu, idx, j);
            int a1 = __shfl_sync(0xffffffffu, idx, j + 1);
            int a2 = __shfl_sync(0xffffffffu, idx, j + 2);
            int a3 = __shfl_sync(0xffffffffu, idx, j + 3);
            union { uint2 u; __half2 h[2]; } v0, v1, v2, v3;
            v0.u = __ldg(&Hv[(size_t)a0 * 32 + lane]);
            v1.u = __ldg(&Hv[(size_t)a1 * 32 + lane]);
            v2.u = __ldg(&Hv[(size_t)a2 * 32 + lane]);
            v3.u = __ldg(&Hv[(size_t)a3 * 32 + lane]);
            float2 p0 = __half22float2(v0.h[0]), q0 = __half22float2(v0.h[1]);
            float2 p1 = __half22float2(v1.h[0]), q1 = __half22float2(v1.h[1]);
            float2 p2 = __half22float2(v2.h[0]), q2 = __half22float2(v2.h[1]);
            float2 p3 = __half22float2(v3.h[0]), q3 = __half22float2(v3.h[1]);
            acc.x += (p0.x + p1.x) + (p2.x + p3.x);
            acc.y += (p0.y + p1.y) + (p2.y + p3.y);
            acc.z += (q0.x + q1.x) + (q2.x + q3.x);
            acc.w += (q0.y + q1.y) + (q2.y + q3.y);
        }
        for (; j < m; j++) {
            int a0 = __shfl_sync(0xffffffffu, idx, j);
            union { uint2 u; __half2 h[2]; } v0;
            v0.u = __ldg(&Hv[(size_t)a0 * 32 + lane]);
            float2 p0 = __half22float2(v0.h[0]), q0 = __half22float2(v0.h[1]);
            acc.x += p0.x; acc.y += p0.y; acc.z += q0.x; acc.w += q0.y;
        }
    }
    float di = g_dinv[w];
    float4 bb = __ldg(&((const float4*)bias)[lane]);
    float4 o;
    o.x = fmaf(di, acc.x, bb.x);
    o.y = fmaf(di, acc.y, bb.y);
    o.z = fmaf(di, acc.z, bb.z);
    o.w = fmaf(di, acc.w, bb.w);
    if (do_relu) {
        o.x = fmaxf(o.x, 0.f); o.y = fmaxf(o.y, 0.f);
        o.z = fmaxf(o.z, 0.f); o.w = fmaxf(o.w, 0.f);
    }
    ((float4*)g_a)[(size_t)w * 32 + lane] = o;
}

// ---------------- fused mean-pool + linear ----------------
__global__ __launch_bounds__(128) void pool_lin_k(const float* __restrict__ Wlin,
                                                  const float* __restrict__ blin,
                                                  int br) {
    int g = blockIdx.x;
    int t = threadIdx.x;  // 128
    int s = g_goff[g];
    int c = g_goff[g + 1] - s;
    float sum = 0.f;
    for (int r = s; r < s + c; r++) sum += g_a[(size_t)r * DH + t];
    __shared__ float m[DH];
    m[t] = sum * (1.f / fmaxf((float)c, 1.f));
    __syncthreads();
    if (t < DOUT) {
        float o = blin[t];
#pragma unroll
        for (int f = 0; f < DH; f++) o = fmaf(m[f], Wlin[f * DOUT + t], o);
        g_emb[br][g * DOUT + t] = o;
    }
}

// ---------------- pairwise distance ----------------
__global__ void final_k(float* __restrict__ out) {
    int g = blockIdx.x, lane = threadIdx.x;  // 32 threads
    float d0 = g_emb[0][g * DOUT + lane]      - g_emb[1][g * DOUT + lane]      + 1e-6f;
    float d1 = g_emb[0][g * DOUT + lane + 32] - g_emb[1][g * DOUT + lane + 32] + 1e-6f;
    float s = d0 * d0 + d1 * d1;
#pragma unroll
    for (int o = 16; o; o >>= 1) s += __shfl_xor_sync(0xffffffffu, s, o);
    if (lane == 0) out[g] = sqrtf(s);
}

// ---------------- host driver ----------------
static void run_branch(const float* x, const int* ei, const int* batch,
                       const float* W1, const float* b1,
                       const float* W2, const float* b2,
                       const float* W3, const float* b3,
                       const float* Wl, const float* bl, int br) {
    const int* src = ei;
    const int* dst = ei + NE;

    zero_k<<<(NN + 1023) / 1024, 1024>>>();
    count_k<<<(NE + 511) / 512, 512>>>(dst);
    offs_k<<<(NN + 255) / 256, 256>>>();
    fill_k<<<(NE + 511) / 512, 512>>>(src, dst);
    gbound_k<<<(NN + 255) / 256, 256>>>(batch);

    gemm_k<<<(NN + 127) / 128, 256>>>(x, W1, 0);
    agg_k<<<(NN + 7) / 8, 256>>>(b1, 1);
    gemm_k<<<(NN + 127) / 128, 256>>>(nullptr, W2, 1);
    agg_k<<<(NN + 7) / 8, 256>>>(b2, 1);
    gemm_k<<<(NN + 127) / 128, 256>>>(nullptr, W3, 1);
    agg_k<<<(NN + 7) / 8, 256>>>(b3, 0);

    pool_lin_k<<<NG, 128>>>(Wl, bl, br);
}

extern "C" void kernel_launch(void* const* d_in, const int* in_sizes, int n_in,
                              void* d_out, int out_size) {
    const float* x1 = (const float*)d_in[0];
    const int*   e1 = (const int*)d_in[1];
    const int*   t1 = (const int*)d_in[2];
    const float* x2 = (const float*)d_in[3];
    const int*   e2 = (const int*)d_in[4];
    const int*   t2 = (const int*)d_in[5];
    const float* W1 = (const float*)d_in[6];
    const float* b1 = (const float*)d_in[7];
    const float* W2 = (const float*)d_in[8];
    const float* b2 = (const float*)d_in[9];
    const float* W3 = (const float*)d_in[10];
    const float* b3 = (const float*)d_in[11];
    const float* Wl = (const float*)d_in[12];
    const float* bl = (const float*)d_in[13];

    run_branch(x1, e1, t1, W1, b1, W2, b2, W3, b3, Wl, bl, 0);
    run_branch(x2, e2, t2, W1, b1, W2, b2, W3, b3, Wl, bl, 1);
    final_k<<<NG, 32>>>((float*)d_out);
}

// round 6
// speedup vs baseline: 1.7809x; 1.3905x over previous
#include <cuda_runtime.h>
#include <cuda_fp16.h>

#define NN 50000
#define NE 1600000
#define NG 512
#define DH 128
#define DOUT 64

// ---------------- scratch (static __device__ — no allocations) ----------------
__device__ int                        g_deg[NN];
__device__ float                      g_dinv[NN];
__device__ int                        g_off[NN];
__device__ int                        g_cur[NN];
__device__ int                        g_total;
__device__ int                        g_csr[NE];
__device__ __align__(16) __half       g_h[NN * DH];    // h' = dinv * (X @ W), fp16
__device__ __align__(16) __half       g_a16[NN * DH];  // activations (fp16)
__device__ __align__(16) __half       g_x16[NN * DH];  // converted layer-1 input
__device__ __align__(16) __half       g_wt[3][DH * DH]; // W^T fp16: wt[n*DH+k]
__device__ int                        g_goff[NG + 1];
__device__ float                      g_emb[2][NG * DOUT];

// ---------------- graph prep ----------------
__global__ void zero_k() {
    int i = blockIdx.x * blockDim.x + threadIdx.x;
    if (i < NN) g_deg[i] = 0;
    if (i == 0) g_total = 0;
}

__global__ void count_k(const int* __restrict__ dst) {
    int e = blockIdx.x * blockDim.x + threadIdx.x;
    if (e < NE) atomicAdd(&g_deg[dst[e]], 1);
}

// scan-free CSR offsets: warp-aggregated atomic chunk assignment + dinv
__global__ void offs_k() {
    int i = blockIdx.x * blockDim.x + threadIdx.x;
    int lane = threadIdx.x & 31;
    int d = (i < NN) ? g_deg[i] : 0;
    int incl = d;
#pragma unroll
    for (int o = 1; o < 32; o <<= 1) {
        int x = __shfl_up_sync(0xffffffffu, incl, o);
        if (lane >= o) incl += x;
    }
    int wsum = __shfl_sync(0xffffffffu, incl, 31);
    int base = 0;
    if (lane == 31) base = atomicAdd(&g_total, wsum);
    base = __shfl_sync(0xffffffffu, base, 31);
    if (i < NN) {
        int p = base + incl - d;
        g_off[i] = p;
        g_cur[i] = p;
        g_dinv[i] = rsqrtf((float)(d + 1));  // +1 self-loop
    }
}

__global__ void fill_k(const int* __restrict__ src, const int* __restrict__ dst) {
    int e = blockIdx.x * blockDim.x + threadIdx.x;
    if (e < NE) {
        int p = atomicAdd(&g_cur[dst[e]], 1);
        g_csr[p] = src[e];
    }
}

// graph segment boundaries from the sorted batch array
__global__ void gbound_k(const int* __restrict__ batch) {
    int i = blockIdx.x * blockDim.x + threadIdx.x;
    if (i >= NN) return;
    int bc = batch[i];
    if (i == 0) {
        for (int g = 0; g <= bc; g++) g_goff[g] = 0;
    } else {
        int bp = batch[i - 1];
        for (int g = bp + 1; g <= bc; g++) g_goff[g] = i;
    }
    if (i == NN - 1) {
        for (int g = bc + 1; g <= NG; g++) g_goff[g] = NN;
    }
}

// ---------------- converters ----------------
__global__ void wconv_k(const float* __restrict__ W, int which) {
    int t = blockIdx.x * blockDim.x + threadIdx.x;  // t = k*DH + n (coalesced read)
    if (t < DH * DH) {
        int k = t >> 7, n = t & 127;
        g_wt[which][n * DH + k] = __float2half(W[t]);
    }
}

__global__ void xconv_k(const float* __restrict__ x) {
    int i = blockIdx.x * blockDim.x + threadIdx.x;  // over NN*DH/4
    if (i < NN * DH / 4) {
        float4 v = ((const float4*)x)[i];
        union { uint2 u; __half2 h[2]; } pk;
        pk.h[0] = __floats2half2_rn(v.x, v.y);
        pk.h[1] = __floats2half2_rn(v.z, v.w);
        ((uint2*)g_x16)[i] = pk.u;
    }
}

// ---------------- GEMM via tensor cores (mma.sync m16n8k16 fp16->fp32) --------
// g_h[i] = fp16( dinv[i] * (A[i] @ W) ), A fp16 [NN,128], W^T fp16 [128,128].
// Block: 128x128 tile, 256 thr = 8 warps (4m x 2n), warp tile 32x64.
// K processed in two 64-wide smem stages. smem pitch 72 halves (36 u32).
// NOTE: operand buffers are __device__ symbols; they MUST be resolved inside
// the kernel (selector args), never passed as host-evaluated pointers.
__device__ __forceinline__ void mma16816(float* c, unsigned a0, unsigned a1,
                                         unsigned a2, unsigned a3,
                                         unsigned b0, unsigned b1) {
    asm volatile(
        "mma.sync.aligned.m16n8k16.row.col.f32.f16.f16.f32 "
        "{%0,%1,%2,%3}, {%4,%5,%6,%7}, {%8,%9}, {%0,%1,%2,%3};"
        : "+f"(c[0]), "+f"(c[1]), "+f"(c[2]), "+f"(c[3])
        : "r"(a0), "r"(a1), "r"(a2), "r"(a3), "r"(b0), "r"(b1));
}

__global__ __launch_bounds__(256) void gemm_k(int from_a, int wsel) {
    const __half* __restrict__ A  = from_a ? g_a16 : g_x16;
    const __half* __restrict__ Wt = g_wt[wsel];

    __shared__ __align__(16) unsigned As32[128 * 36];
    __shared__ __align__(16) unsigned Ws32[128 * 36];

    int row0 = blockIdx.x * 128;
    int t = threadIdx.x;
    int lane = t & 31;
    int wid = t >> 5;
    int warp_m = wid & 3;   // 4 warps over rows (32 each)
    int warp_n = wid >> 2;  // 2 warps over cols (64 each)
    int g = lane >> 2;      // 0..7
    int tig = lane & 3;     // 0..3

    float c[2][8][4];
#pragma unroll
    for (int mt = 0; mt < 2; mt++)
#pragma unroll
        for (int nt = 0; nt < 8; nt++)
#pragma unroll
            for (int j = 0; j < 4; j++) c[mt][nt][j] = 0.f;

    for (int ks = 0; ks < 2; ks++) {
        __syncthreads();
        // load A tile: 128 rows x 64 halves (cols ks*64..)
#pragma unroll
        for (int i = 0; i < 4; i++) {
            int idx = t + i * 256;           // [0,1024)
            int r = idx >> 3, q = idx & 7;
            uint4 v = make_uint4(0u, 0u, 0u, 0u);
            int gr = row0 + r;
            if (gr < NN) v = *(const uint4*)(A + (size_t)gr * DH + ks * 64 + q * 8);
            *(uint4*)&As32[r * 36 + q * 4] = v;
        }
        // load W^T tile: 128 cols x 64 halves
#pragma unroll
        for (int i = 0; i < 4; i++) {
            int idx = t + i * 256;
            int n = idx >> 3, q = idx & 7;
            uint4 v = *(const uint4*)(Wt + (size_t)n * DH + ks * 64 + q * 8);
            *(uint4*)&Ws32[n * 36 + q * 4] = v;
        }
        __syncthreads();

#pragma unroll
        for (int kc = 0; kc < 4; kc++) {
            unsigned a[2][4];
#pragma unroll
            for (int mt = 0; mt < 2; mt++) {
                int rb = warp_m * 32 + mt * 16;
                a[mt][0] = As32[(rb + g) * 36 + kc * 8 + tig];
                a[mt][1] = As32[(rb + g + 8) * 36 + kc * 8 + tig];
                a[mt][2] = As32[(rb + g) * 36 + kc * 8 + tig + 4];
                a[mt][3] = As32[(rb + g + 8) * 36 + kc * 8 + tig + 4];
            }
#pragma unroll
            for (int nt = 0; nt < 8; nt++) {
                int nb = warp_n * 64 + nt * 8;
                unsigned b0 = Ws32[(nb + g) * 36 + kc * 8 + tig];
                unsigned b1 = Ws32[(nb + g) * 36 + kc * 8 + tig + 4];
                mma16816(c[0][nt], a[0][0], a[0][1], a[0][2], a[0][3], b0, b1);
                mma16816(c[1][nt], a[1][0], a[1][1], a[1][2], a[1][3], b0, b1);
            }
        }
    }

    // epilogue: scale by dinv, write fp16
#pragma unroll
    for (int mt = 0; mt < 2; mt++) {
        int r0 = row0 + warp_m * 32 + mt * 16 + g;
        int r1 = r0 + 8;
        float s0 = (r0 < NN) ? g_dinv[r0] : 0.f;
        float s1 = (r1 < NN) ? g_dinv[r1] : 0.f;
#pragma unroll
        for (int nt = 0; nt < 8; nt++) {
            int col = warp_n * 64 + nt * 8 + 2 * tig;
            float* cc = c[mt][nt];
            if (r0 < NN)
                *(__half2*)(g_h + (size_t)r0 * DH + col) =
                    __floats2half2_rn(s0 * cc[0], s0 * cc[1]);
            if (r1 < NN)
                *(__half2*)(g_h + (size_t)r1 * DH + col) =
                    __floats2half2_rn(s1 * cc[2], s1 * cc[3]);
        }
    }
}

// ---------------- aggregation: warp-per-node CSR gather-reduce (fp16 rows) -----
// g_a16[i] = act( dinv[i] * (sum_{src in N(i)} h'[src] + h'[i]) + b )
__global__ __launch_bounds__(256, 8) void agg_k(const float* __restrict__ bias,
                                                int do_relu) {
    int w = blockIdx.x * 8 + (threadIdx.x >> 5);
    if (w >= NN) return;
    int lane = threadIdx.x & 31;
    const uint2* __restrict__ Hv = (const uint2*)g_h;  // 4 halves per lane

    union { uint2 u; __half2 h[2]; } v;
    v.u = __ldg(&Hv[(size_t)w * 32 + lane]);  // self-loop term
    float2 f0 = __half22float2(v.h[0]);
    float2 f1 = __half22float2(v.h[1]);
    float4 acc = make_float4(f0.x, f0.y, f1.x, f1.y);

    int s0 = g_off[w];
    int s1 = s0 + g_deg[w];
    for (int base = s0; base < s1; base += 32) {
        int e = base + lane;
        int idx = (e < s1) ? __ldg(&g_csr[e]) : 0;
        int m = min(32, s1 - base);
        int j = 0;
        for (; j + 4 <= m; j += 4) {
            int a0 = __shfl_sync(0xffffffffu, idx, j);
            int a1 = __shfl_sync(0xffffffffu, idx, j + 1);
            int a2 = __shfl_sync(0xffffffffu, idx, j + 2);
            int a3 = __shfl_sync(0xffffffffu, idx, j + 3);
            union { uint2 u; __half2 h[2]; } v0, v1, v2, v3;
            v0.u = __ldg(&Hv[(size_t)a0 * 32 + lane]);
            v1.u = __ldg(&Hv[(size_t)a1 * 32 + lane]);
            v2.u = __ldg(&Hv[(size_t)a2 * 32 + lane]);
            v3.u = __ldg(&Hv[(size_t)a3 * 32 + lane]);
            float2 p0 = __half22float2(v0.h[0]), q0 = __half22float2(v0.h[1]);
            float2 p1 = __half22float2(v1.h[0]), q1 = __half22float2(v1.h[1]);
            float2 p2 = __half22float2(v2.h[0]), q2 = __half22float2(v2.h[1]);
            float2 p3 = __half22float2(v3.h[0]), q3 = __half22float2(v3.h[1]);
            acc.x += (p0.x + p1.x) + (p2.x + p3.x);
            acc.y += (p0.y + p1.y) + (p2.y + p3.y);
            acc.z += (q0.x + q1.x) + (q2.x + q3.x);
            acc.w += (q0.y + q1.y) + (q2.y + q3.y);
        }
        for (; j < m; j++) {
            int a0 = __shfl_sync(0xffffffffu, idx, j);
            union { uint2 u; __half2 h[2]; } v0;
            v0.u = __ldg(&Hv[(size_t)a0 * 32 + lane]);
            float2 p0 = __half22float2(v0.h[0]), q0 = __half22float2(v0.h[1]);
            acc.x += p0.x; acc.y += p0.y; acc.z += q0.x; acc.w += q0.y;
        }
    }
    float di = g_dinv[w];
    float4 bb = __ldg(&((const float4*)bias)[lane]);
    float4 o;
    o.x = fmaf(di, acc.x, bb.x);
    o.y = fmaf(di, acc.y, bb.y);
    o.z = fmaf(di, acc.z, bb.z);
    o.w = fmaf(di, acc.w, bb.w);
    if (do_relu) {
        o.x = fmaxf(o.x, 0.f); o.y = fmaxf(o.y, 0.f);
        o.z = fmaxf(o.z, 0.f); o.w = fmaxf(o.w, 0.f);
    }
    union { uint2 u; __half2 h[2]; } pk;
    pk.h[0] = __floats2half2_rn(o.x, o.y);
    pk.h[1] = __floats2half2_rn(o.z, o.w);
    ((uint2*)g_a16)[(size_t)w * 32 + lane] = pk.u;
}

// ---------------- fused mean-pool + linear ----------------
__global__ __launch_bounds__(128) void pool_lin_k(const float* __restrict__ Wlin,
                                                  const float* __restrict__ blin,
                                                  int br) {
    int g = blockIdx.x;
    int t = threadIdx.x;  // 128
    int s = g_goff[g];
    int c = g_goff[g + 1] - s;
    float sum = 0.f;
    for (int r = s; r < s + c; r++) sum += __half2float(g_a16[(size_t)r * DH + t]);
    __shared__ float m[DH];
    m[t] = sum * (1.f / fmaxf((float)c, 1.f));
    __syncthreads();
    if (t < DOUT) {
        float o = blin[t];
#pragma unroll
        for (int f = 0; f < DH; f++) o = fmaf(m[f], Wlin[f * DOUT + t], o);
        g_emb[br][g * DOUT + t] = o;
    }
}

// ---------------- pairwise distance ----------------
__global__ void final_k(float* __restrict__ out) {
    int g = blockIdx.x, lane = threadIdx.x;  // 32 threads
    float d0 = g_emb[0][g * DOUT + lane]      - g_emb[1][g * DOUT + lane]      + 1e-6f;
    float d1 = g_emb[0][g * DOUT + lane + 32] - g_emb[1][g * DOUT + lane + 32] + 1e-6f;
    float s = d0 * d0 + d1 * d1;
#pragma unroll
    for (int o = 16; o; o >>= 1) s += __shfl_xor_sync(0xffffffffu, s, o);
    if (lane == 0) out[g] = sqrtf(s);
}

// ---------------- host driver ----------------
static void run_branch(const float* x, const int* ei, const int* batch,
                       const float* b1, const float* b2, const float* b3,
                       const float* Wl, const float* bl, int br) {
    const int* src = ei;
    const int* dst = ei + NE;

    zero_k<<<(NN + 1023) / 1024, 1024>>>();
    count_k<<<(NE + 511) / 512, 512>>>(dst);
    offs_k<<<(NN + 255) / 256, 256>>>();
    fill_k<<<(NE + 511) / 512, 512>>>(src, dst);
    gbound_k<<<(NN + 255) / 256, 256>>>(batch);
    xconv_k<<<(NN * DH / 4 + 255) / 256, 256>>>(x);

    gemm_k<<<(NN + 127) / 128, 256>>>(0, 0);
    agg_k<<<(NN + 7) / 8, 256>>>(b1, 1);
    gemm_k<<<(NN + 127) / 128, 256>>>(1, 1);
    agg_k<<<(NN + 7) / 8, 256>>>(b2, 1);
    gemm_k<<<(NN + 127) / 128, 256>>>(1, 2);
    agg_k<<<(NN + 7) / 8, 256>>>(b3, 0);

    pool_lin_k<<<NG, 128>>>(Wl, bl, br);
}

extern "C" void kernel_launch(void* const* d_in, const int* in_sizes, int n_in,
                              void* d_out, int out_size) {
    const float* x1 = (const float*)d_in[0];
    const int*   e1 = (const int*)d_in[1];
    const int*   t1 = (const int*)d_in[2];
    const float* x2 = (const float*)d_in[3];
    const int*   e2 = (const int*)d_in[4];
    const int*   t2 = (const int*)d_in[5];
    const float* W1 = (const float*)d_in[6];
    const float* b1 = (const float*)d_in[7];
    const float* W2 = (const float*)d_in[8];
    const float* b2 = (const float*)d_in[9];
    const float* W3 = (const float*)d_in[10];
    const float* b3 = (const float*)d_in[11];
    const float* Wl = (const float*)d_in[12];
    const float* bl = (const float*)d_in[13];

    wconv_k<<<(DH * DH + 255) / 256, 256>>>(W1, 0);
    wconv_k<<<(DH * DH + 255) / 256, 256>>>(W2, 1);
    wconv_k<<<(DH * DH + 255) / 256, 256>>>(W3, 2);

    run_branch(x1, e1, t1, b1, b2, b3, Wl, bl, 0);
    run_branch(x2, e2, t2, b1, b2, b3, Wl, bl, 1);
    final_k<<<NG, 32>>>((float*)d_out);
}

// round 8
// speedup vs baseline: 1.9668x; 1.1044x over previous
#include <cuda_runtime.h>
#include <cuda_fp16.h>

#define NN 50000
#define NE 1600000
#define NG 512
#define DH 128
#define DOUT 64

// ---------------- scratch (static __device__ — no allocations) ----------------
__device__ int                        g_deg[2][NN];
__device__ float                      g_dinv[2][NN];
__device__ int                        g_off[2][NN];
__device__ int                        g_cur[2][NN];
__device__ int                        g_total[2];
__device__ int                        g_csr[2][NE];
__device__ __align__(16) __half       g_h[2][NN * DH];    // h' = dinv*(X@W), fp16
__device__ __align__(16) __half       g_a16[2][NN * DH];  // activations (fp16)
__device__ __align__(16) __half       g_x16[2][NN * DH];  // converted layer-1 input
__device__ __align__(16) __half       g_wt[3][DH * DH];   // W^T fp16: wt[n*DH+k]
__device__ int                        g_goff[2][NG + 1];
__device__ float                      g_emb[2][NG * DOUT];

// ---------------- graph prep (both branches per launch) ----------------
__global__ void zero_k() {
    int i = blockIdx.x * blockDim.x + threadIdx.x;
    if (i < NN) { g_deg[0][i] = 0; g_deg[1][i] = 0; }
    if (i == 0) { g_total[0] = 0; g_total[1] = 0; }
}

__global__ void count_k(const int* __restrict__ dst0, const int* __restrict__ dst1) {
    int e = blockIdx.x * blockDim.x + threadIdx.x;
    if (e < NE) {
        atomicAdd(&g_deg[0][dst0[e]], 1);
        atomicAdd(&g_deg[1][dst1[e]], 1);
    }
}

// scan-free CSR offsets: warp-aggregated atomic chunk assignment + dinv
__global__ void offs_k() {
    int br = blockIdx.y;
    int i = blockIdx.x * blockDim.x + threadIdx.x;
    int lane = threadIdx.x & 31;
    int d = (i < NN) ? g_deg[br][i] : 0;
    int incl = d;
#pragma unroll
    for (int o = 1; o < 32; o <<= 1) {
        int x = __shfl_up_sync(0xffffffffu, incl, o);
        if (lane >= o) incl += x;
    }
    int wsum = __shfl_sync(0xffffffffu, incl, 31);
    int base = 0;
    if (lane == 31) base = atomicAdd(&g_total[br], wsum);
    base = __shfl_sync(0xffffffffu, base, 31);
    if (i < NN) {
        int p = base + incl - d;
        g_off[br][i] = p;
        g_cur[br][i] = p;
        g_dinv[br][i] = rsqrtf((float)(d + 1));  // +1 self-loop
    }
}

__global__ void fill_k(const int* __restrict__ src0, const int* __restrict__ dst0,
                       const int* __restrict__ src1, const int* __restrict__ dst1) {
    int e = blockIdx.x * blockDim.x + threadIdx.x;
    if (e < NE) {
        int p0 = atomicAdd(&g_cur[0][dst0[e]], 1);
        g_csr[0][p0] = src0[e];
        int p1 = atomicAdd(&g_cur[1][dst1[e]], 1);
        g_csr[1][p1] = src1[e];
    }
}

// graph segment boundaries from the sorted batch arrays
__global__ void gbound_k(const int* __restrict__ b0, const int* __restrict__ b1) {
    int br = blockIdx.y;
    const int* __restrict__ batch = br ? b1 : b0;
    int i = blockIdx.x * blockDim.x + threadIdx.x;
    if (i >= NN) return;
    int bc = batch[i];
    if (i == 0) {
        for (int g = 0; g <= bc; g++) g_goff[br][g] = 0;
    } else {
        int bp = batch[i - 1];
        for (int g = bp + 1; g <= bc; g++) g_goff[br][g] = i;
    }
    if (i == NN - 1) {
        for (int g = bc + 1; g <= NG; g++) g_goff[br][g] = NN;
    }
}

// ---------------- converters ----------------
__global__ void wconv_k(const float* __restrict__ W1, const float* __restrict__ W2,
                        const float* __restrict__ W3) {
    int t = blockIdx.x * blockDim.x + threadIdx.x;  // t = k*DH + n (coalesced read)
    if (t < DH * DH) {
        int k = t >> 7, n = t & 127;
        g_wt[0][n * DH + k] = __float2half(W1[t]);
        g_wt[1][n * DH + k] = __float2half(W2[t]);
        g_wt[2][n * DH + k] = __float2half(W3[t]);
    }
}

__global__ void xconv_k(const float* __restrict__ x0, const float* __restrict__ x1) {
    int br = blockIdx.y;
    const float* __restrict__ x = br ? x1 : x0;
    int i = blockIdx.x * blockDim.x + threadIdx.x;  // over NN*DH/4
    if (i < NN * DH / 4) {
        float4 v = ((const float4*)x)[i];
        union { uint2 u; __half2 h[2]; } pk;
        pk.h[0] = __floats2half2_rn(v.x, v.y);
        pk.h[1] = __floats2half2_rn(v.z, v.w);
        ((uint2*)g_x16[br])[i] = pk.u;
    }
}

// ---------------- GEMM via tensor cores (mma.sync m16n8k16 fp16->fp32) --------
// g_h[br][i] = fp16( dinv[i] * (A[i] @ W) ). Block: 128x128 tile, 256 thr =
// 8 warps (4m x 2n). K in two 64-wide smem stages, pitch 36 u32 (bank-clean).
// __device__ buffers resolved INSIDE the kernel (selector args only).
__device__ __forceinline__ void mma16816(float* c, unsigned a0, unsigned a1,
                                         unsigned a2, unsigned a3,
                                         unsigned b0, unsigned b1) {
    asm volatile(
        "mma.sync.aligned.m16n8k16.row.col.f32.f16.f16.f32 "
        "{%0,%1,%2,%3}, {%4,%5,%6,%7}, {%8,%9}, {%0,%1,%2,%3};"
        : "+f"(c[0]), "+f"(c[1]), "+f"(c[2]), "+f"(c[3])
        : "r"(a0), "r"(a1), "r"(a2), "r"(a3), "r"(b0), "r"(b1));
}

__global__ __launch_bounds__(256) void gemm_k(int from_a, int wsel) {
    int br = blockIdx.y;
    const __half* __restrict__ A  = from_a ? g_a16[br] : g_x16[br];
    const __half* __restrict__ Wt = g_wt[wsel];

    __shared__ __align__(16) unsigned As32[128 * 36];
    __shared__ __align__(16) unsigned Ws32[128 * 36];

    int row0 = blockIdx.x * 128;
    int t = threadIdx.x;
    int lane = t & 31;
    int wid = t >> 5;
    int warp_m = wid & 3;   // 4 warps over rows (32 each)
    int warp_n = wid >> 2;  // 2 warps over cols (64 each)
    int g = lane >> 2;      // 0..7
    int tig = lane & 3;     // 0..3

    float c[2][8][4];
#pragma unroll
    for (int mt = 0; mt < 2; mt++)
#pragma unroll
        for (int nt = 0; nt < 8; nt++)
#pragma unroll
            for (int j = 0; j < 4; j++) c[mt][nt][j] = 0.f;

    for (int ks = 0; ks < 2; ks++) {
        __syncthreads();
#pragma unroll
        for (int i = 0; i < 4; i++) {
            int idx = t + i * 256;           // [0,1024)
            int r = idx >> 3, q = idx & 7;
            uint4 v = make_uint4(0u, 0u, 0u, 0u);
            int gr = row0 + r;
            if (gr < NN) v = *(const uint4*)(A + (size_t)gr * DH + ks * 64 + q * 8);
            *(uint4*)&As32[r * 36 + q * 4] = v;
        }
#pragma unroll
        for (int i = 0; i < 4; i++) {
            int idx = t + i * 256;
            int n = idx >> 3, q = idx & 7;
            uint4 v = *(const uint4*)(Wt + (size_t)n * DH + ks * 64 + q * 8);
            *(uint4*)&Ws32[n * 36 + q * 4] = v;
        }
        __syncthreads();

#pragma unroll
        for (int kc = 0; kc < 4; kc++) {
            unsigned a[2][4];
#pragma unroll
            for (int mt = 0; mt < 2; mt++) {
                int rb = warp_m * 32 + mt * 16;
                a[mt][0] = As32[(rb + g) * 36 + kc * 8 + tig];
                a[mt][1] = As32[(rb + g + 8) * 36 + kc * 8 + tig];
                a[mt][2] = As32[(rb + g) * 36 + kc * 8 + tig + 4];
                a[mt][3] = As32[(rb + g + 8) * 36 + kc * 8 + tig + 4];
            }
#pragma unroll
            for (int nt = 0; nt < 8; nt++) {
                int nb = warp_n * 64 + nt * 8;
                unsigned b0 = Ws32[(nb + g) * 36 + kc * 8 + tig];
                unsigned b1 = Ws32[(nb + g) * 36 + kc * 8 + tig + 4];
                mma16816(c[0][nt], a[0][0], a[0][1], a[0][2], a[0][3], b0, b1);
                mma16816(c[1][nt], a[1][0], a[1][1], a[1][2], a[1][3], b0, b1);
            }
        }
    }

#pragma unroll
    for (int mt = 0; mt < 2; mt++) {
        int r0 = row0 + warp_m * 32 + mt * 16 + g;
        int r1 = r0 + 8;
        float s0 = (r0 < NN) ? g_dinv[br][r0] : 0.f;
        float s1 = (r1 < NN) ? g_dinv[br][r1] : 0.f;
#pragma unroll
        for (int nt = 0; nt < 8; nt++) {
            int col = warp_n * 64 + nt * 8 + 2 * tig;
            float* cc = c[mt][nt];
            if (r0 < NN)
                *(__half2*)(g_h[br] + (size_t)r0 * DH + col) =
                    __floats2half2_rn(s0 * cc[0], s0 * cc[1]);
            if (r1 < NN)
                *(__half2*)(g_h[br] + (size_t)r1 * DH + col) =
                    __floats2half2_rn(s1 * cc[2], s1 * cc[3]);
        }
    }
}

// ---------------- aggregation: warp-per-node CSR gather-reduce (fp16 rows) -----
// g_a16[br][i] = act( dinv[i] * (sum_{src in N(i)} h'[src] + h'[i]) + b )
__global__ __launch_bounds__(256, 8) void agg_k(const float* __restrict__ bias,
                                                int do_relu) {
    int br = blockIdx.y;
    int w = blockIdx.x * 8 + (threadIdx.x >> 5);
    if (w >= NN) return;
    int lane = threadIdx.x & 31;
    const uint2* __restrict__ Hv = (const uint2*)g_h[br];  // 4 halves per lane
    const int* __restrict__ csr = g_csr[br];

    union { uint2 u; __half2 h[2]; } v;
    v.u = __ldg(&Hv[(size_t)w * 32 + lane]);  // self-loop term
    float2 f0 = __half22float2(v.h[0]);
    float2 f1 = __half22float2(v.h[1]);
    float4 acc = make_float4(f0.x, f0.y, f1.x, f1.y);

    int s0 = g_off[br][w];
    int s1 = s0 + g_deg[br][w];
    for (int base = s0; base < s1; base += 32) {
        int e = base + lane;
        int idx = (e < s1) ? __ldg(&csr[e]) : 0;
        int m = min(32, s1 - base);
        int j = 0;
        for (; j + 4 <= m; j += 4) {
            int a0 = __shfl_sync(0xffffffffu, idx, j);
            int a1 = __shfl_sync(0xffffffffu, idx, j + 1);
            int a2 = __shfl_sync(0xffffffffu, idx, j + 2);
            int a3 = __shfl_sync(0xffffffffu, idx, j + 3);
            union { uint2 u; __half2 h[2]; } v0, v1, v2, v3;
            v0.u = __ldg(&Hv[(size_t)a0 * 32 + lane]);
            v1.u = __ldg(&Hv[(size_t)a1 * 32 + lane]);
            v2.u = __ldg(&Hv[(size_t)a2 * 32 + lane]);
            v3.u = __ldg(&Hv[(size_t)a3 * 32 + lane]);
            float2 p0 = __half22float2(v0.h[0]), q0 = __half22float2(v0.h[1]);
            float2 p1 = __half22float2(v1.h[0]), q1 = __half22float2(v1.h[1]);
            float2 p2 = __half22float2(v2.h[0]), q2 = __half22float2(v2.h[1]);
            float2 p3 = __half22float2(v3.h[0]), q3 = __half22float2(v3.h[1]);
            acc.x += (p0.x + p1.x) + (p2.x + p3.x);
            acc.y += (p0.y + p1.y) + (p2.y + p3.y);
            acc.z += (q0.x + q1.x) + (q2.x + q3.x);
            acc.w += (q0.y + q1.y) + (q2.y + q3.y);
        }
        for (; j < m; j++) {
            int a0 = __shfl_sync(0xffffffffu, idx, j);
            union { uint2 u; __half2 h[2]; } v0;
            v0.u = __ldg(&Hv[(size_t)a0 * 32 + lane]);
            float2 p0 = __half22float2(v0.h[0]), q0 = __half22float2(v0.h[1]);
            acc.x += p0.x; acc.y += p0.y; acc.z += q0.x; acc.w += q0.y;
        }
    }
    float di = g_dinv[br][w];
    float4 bb = __ldg(&((const float4*)bias)[lane]);
    float4 o;
    o.x = fmaf(di, acc.x, bb.x);
    o.y = fmaf(di, acc.y, bb.y);
    o.z = fmaf(di, acc.z, bb.z);
    o.w = fmaf(di, acc.w, bb.w);
    if (do_relu) {
        o.x = fmaxf(o.x, 0.f); o.y = fmaxf(o.y, 0.f);
        o.z = fmaxf(o.z, 0.f); o.w = fmaxf(o.w, 0.f);
    }
    union { uint2 u; __half2 h[2]; } pk;
    pk.h[0] = __floats2half2_rn(o.x, o.y);
    pk.h[1] = __floats2half2_rn(o.z, o.w);
    ((uint2*)g_a16[br])[(size_t)w * 32 + lane] = pk.u;
}

// ---------------- fused mean-pool + linear ----------------
__global__ __launch_bounds__(128) void pool_lin_k(const float* __restrict__ Wlin,
                                                  const float* __restrict__ blin) {
    int br = blockIdx.y;
    int g = blockIdx.x;
    int t = threadIdx.x;  // 128
    int s = g_goff[br][g];
    int c = g_goff[br][g + 1] - s;
    float sum = 0.f;
    for (int r = s; r < s + c; r++) sum += __half2float(g_a16[br][(size_t)r * DH + t]);
    __shared__ float m[DH];
    m[t] = sum * (1.f / fmaxf((float)c, 1.f));
    __syncthreads();
    if (t < DOUT) {
        float o = blin[t];
#pragma unroll
        for (int f = 0; f < DH; f++) o = fmaf(m[f], Wlin[f * DOUT + t], o);
        g_emb[br][g * DOUT + t] = o;
    }
}

// ---------------- pairwise distance ----------------
__global__ void final_k(float* __restrict__ out) {
    int g = blockIdx.x, lane = threadIdx.x;  // 32 threads
    float d0 = g_emb[0][g * DOUT + lane]      - g_emb[1][g * DOUT + lane]      + 1e-6f;
    float d1 = g_emb[0][g * DOUT + lane + 32] - g_emb[1][g * DOUT + lane + 32] + 1e-6f;
    float s = d0 * d0 + d1 * d1;
#pragma unroll
    for (int o = 16; o; o >>= 1) s += __shfl_xor_sync(0xffffffffu, s, o);
    if (lane == 0) out[g] = sqrtf(s);
}

// ---------------- host driver ----------------
extern "C" void kernel_launch(void* const* d_in, const int* in_sizes, int n_in,
                              void* d_out, int out_size) {
    const float* x1 = (const float*)d_in[0];
    const int*   e1 = (const int*)d_in[1];
    const int*   t1 = (const int*)d_in[2];
    const float* x2 = (const float*)d_in[3];
    const int*   e2 = (const int*)d_in[4];
    const int*   t2 = (const int*)d_in[5];
    const float* W1 = (const float*)d_in[6];
    const float* b1 = (const float*)d_in[7];
    const float* W2 = (const float*)d_in[8];
    const float* b2 = (const float*)d_in[9];
    const float* W3 = (const float*)d_in[10];
    const float* b3 = (const float*)d_in[11];
    const float* Wl = (const float*)d_in[12];
    const float* bl = (const float*)d_in[13];

    const int *src1 = e1, *dst1 = e1 + NE;
    const int *src2 = e2, *dst2 = e2 + NE;

    dim3 y2;

    wconv_k<<<(DH * DH + 255) / 256, 256>>>(W1, W2, W3);
    zero_k<<<(NN + 1023) / 1024, 1024>>>();
    count_k<<<(NE + 255) / 256, 256>>>(dst1, dst2);
    offs_k<<<dim3((NN + 255) / 256, 2), 256>>>();
    fill_k<<<(NE + 255) / 256, 256>>>(src1, dst1, src2, dst2);
    gbound_k<<<dim3((NN + 255) / 256, 2), 256>>>(t1, t2);
    xconv_k<<<dim3((NN * DH / 4 + 255) / 256, 2), 256>>>(x1, x2);

    gemm_k<<<dim3((NN + 127) / 128, 2), 256>>>(0, 0);
    agg_k<<<dim3((NN + 7) / 8, 2), 256>>>(b1, 1);
    gemm_k<<<dim3((NN + 127) / 128, 2), 256>>>(1, 1);
    agg_k<<<dim3((NN + 7) / 8, 2), 256>>>(b2, 1);
    gemm_k<<<dim3((NN + 127) / 128, 2), 256>>>(1, 2);
    agg_k<<<dim3((NN + 7) / 8, 2), 256>>>(b3, 0);

    pool_lin_k<<<dim3(NG, 2), 128>>>(Wl, bl);
    final_k<<<NG, 32>>>((float*)d_out);
}